// round 15
// baseline (speedup 1.0000x reference)
#include <cuda_runtime.h>
#include <cuda_bf16.h>
#include <cstdint>

#define AN 9216      // N = 96*96
#define HH 96
#define WW 96
#define FD 64
#define PW 98        // padded width
#define PAN (PW*PW)  // padded plane = 9604

// ---------------- scratch (device globals; no allocation allowed) ------------
__device__ float g_h [3*FD*PAN];          // padded extractor hidden
__device__ float g_f [3*FD*AN];           // features f1,f2,f3 (unpadded)
__device__ __nv_bfloat16 g_QT [AN*8];     // [n][8] (pre-scaled by log2e)
__device__ __nv_bfloat16 g_KT1[AN*8];
__device__ __nv_bfloat16 g_KT3[AN*8];
__device__ __nv_bfloat16 g_V1 [AN*FD];    // [key][64]
__device__ __nv_bfloat16 g_V3 [AN*FD];
__device__ float g_oP [4*FD*AN];          // partial O: [pca*2+half][ch][n]
__device__ float g_rsP[4*AN];             // partial rowsums
__device__ float g_fus[FD*PAN];           // padded
__device__ float g_fh [FD*PAN];           // padded

// ---------------- helpers -----------------------------------------------------
__device__ __forceinline__ uint32_t smem_u32(const void* p) {
    uint32_t a;
    asm("{ .reg .u64 t; cvta.to.shared.u64 t, %1; cvt.u32.u64 %0, t; }" : "=r"(a) : "l"(p));
    return a;
}
__device__ __forceinline__ unsigned long long pk2(float lo, float hi) {
    unsigned long long r;
    asm("mov.b64 %0, {%1, %2};" : "=l"(r) : "f"(lo), "f"(hi));
    return r;
}
__device__ __forceinline__ void upk2(unsigned long long v, float& lo, float& hi) {
    asm("mov.b64 {%0, %1}, %2;" : "=f"(lo), "=f"(hi) : "l"(v));
}
__device__ __forceinline__ unsigned long long fma2(unsigned long long a,
                                                   unsigned long long b,
                                                   unsigned long long c) {
    unsigned long long d;
    asm("fma.rn.f32x2 %0, %1, %2, %3;" : "=l"(d) : "l"(a), "l"(b), "l"(c));
    return d;
}
__device__ __forceinline__ unsigned long long add2(unsigned long long a,
                                                   unsigned long long b) {
    unsigned long long d;
    asm("add.rn.f32x2 %0, %1, %2;" : "=l"(d) : "l"(a), "l"(b));
    return d;
}
__device__ __forceinline__ void mma_s8(float c[4], uint32_t a0, uint32_t a1, uint32_t b) {
    asm("mma.sync.aligned.m16n8k8.row.col.f32.bf16.bf16.f32 "
        "{%0,%1,%2,%3},{%4,%5},{%6},{%0,%1,%2,%3};"
        : "+f"(c[0]), "+f"(c[1]), "+f"(c[2]), "+f"(c[3])
        : "r"(a0), "r"(a1), "r"(b));
}
__device__ __forceinline__ void mma_pv(float c[4], const uint32_t a[4], uint32_t b0, uint32_t b1) {
    asm("mma.sync.aligned.m16n8k16.row.col.f32.bf16.bf16.f32 "
        "{%0,%1,%2,%3},{%4,%5,%6,%7},{%8,%9},{%0,%1,%2,%3};"
        : "+f"(c[0]), "+f"(c[1]), "+f"(c[2]), "+f"(c[3])
        : "r"(a[0]), "r"(a[1]), "r"(a[2]), "r"(a[3]), "r"(b0), "r"(b1));
}
__device__ __forceinline__ void ldsm4t(uint32_t r[4], uint32_t addr) {
    asm volatile("ldmatrix.sync.aligned.m8n8.x4.trans.shared.b16 {%0,%1,%2,%3}, [%4];"
                 : "=r"(r[0]), "=r"(r[1]), "=r"(r[2]), "=r"(r[3]) : "r"(addr));
}
__device__ __forceinline__ uint32_t pkbf(float lo, float hi) {
    __nv_bfloat162 h2 = __floats2bfloat162_rn(lo, hi);
    return *reinterpret_cast<uint32_t*>(&h2);
}
__device__ __forceinline__ void cpa16(uint32_t dst, const void* src) {
    asm volatile("cp.async.cg.shared.global [%0], [%1], 16;" :: "r"(dst), "l"(src) : "memory");
}
#define CPA_COMMIT() asm volatile("cp.async.commit_group;" ::: "memory")
#define CPA_WAIT0()  asm volatile("cp.async.wait_group 0;" ::: "memory")

// zero one padded plane's ring (388 elems) with nt threads
__device__ __forceinline__ void zero_ring(float* base, int t, int nt) {
    for (int i = t; i < 388; i += nt) {
        if (i < 98)       base[i] = 0.0f;
        else if (i < 196) base[97 * PW + (i - 98)] = 0.0f;
        else if (i < 292) base[(i - 196 + 1) * PW] = 0.0f;
        else              base[(i - 292 + 1) * PW + 97] = 0.0f;
    }
}

// ---------------- conv 3->64 from raw NCHW input, writes PADDED --------------
template<int CPB>
__global__ void convA_k(const float* __restrict__ in0, const float* __restrict__ in1,
                        const float* __restrict__ in2,
                        const float* __restrict__ w, const float* __restrict__ bias,
                        float* __restrict__ out) {
    __shared__ float ws[CPB * 3 * 9];
    const int oc0 = blockIdx.y * CPB;
    for (int i = threadIdx.x; i < CPB * 3 * 9; i += blockDim.x)
        ws[i] = w[oc0 * 3 * 9 + i];
    __syncthreads();

    const int z = blockIdx.z;
    const float* in = (z == 0) ? in0 : (z == 1) ? in1 : in2;
    float* outp = out + (long)z * FD * PAN;

    if (blockIdx.x < 8)
        zero_ring(outp + (long)(oc0 + blockIdx.x) * PAN, threadIdx.x, 128);

    const int p = blockIdx.x * blockDim.x + threadIdx.x;
    const int y = p / WW, x = p % WW;

    float acc[CPB];
#pragma unroll
    for (int k = 0; k < CPB; k++) acc[k] = bias[oc0 + k];

#pragma unroll
    for (int c = 0; c < 3; c++) {
        float v[9];
#pragma unroll
        for (int dy = 0; dy < 3; dy++) {
            const int yy = y + dy - 1;
#pragma unroll
            for (int dx = 0; dx < 3; dx++) {
                const int xx = x + dx - 1;
                v[dy * 3 + dx] = (yy >= 0 && yy < HH && xx >= 0 && xx < WW)
                                     ? in[c * AN + yy * WW + xx] : 0.0f;
            }
        }
#pragma unroll
        for (int k = 0; k < CPB; k++) {
            const float* wk = ws + k * 27 + c * 9;
#pragma unroll
            for (int j = 0; j < 9; j++) acc[k] += wk[j] * v[j];
        }
    }
#pragma unroll
    for (int k = 0; k < CPB; k++)
        outp[(oc0 + k) * PAN + (y + 1) * PW + (x + 1)] = fmaxf(acc[k], 0.0f);
}

// ---------------- 64->COUT conv from PADDED input, 2x2 px/thread, f32x2 ------
template<int CPB, bool RELU, bool TO_PAD>
__global__ __launch_bounds__(128) void convP_k(
    const float* __restrict__ in, const float* __restrict__ w,
    const float* __restrict__ bias, float* __restrict__ out) {
    __shared__ __align__(8) float ws2[FD * 9 * CPB];   // [c*9+j][k]
    const int oc0 = blockIdx.y * CPB;
    for (int i = threadIdx.x; i < CPB * FD * 9; i += blockDim.x) {
        const int k = i / (FD * 9), rem = i % (FD * 9);
        ws2[rem * CPB + k] = w[oc0 * FD * 9 + i];
    }
    __syncthreads();

    const float* inz  = in + (long)blockIdx.z * FD * PAN;
    float* outp = out + (long)blockIdx.z * FD * AN;

    const int cell = blockIdx.x * blockDim.x + threadIdx.x;   // 0..2303
    const int cx = cell % 48, cy = cell / 48;
    const int x = 2 * cx, y = 2 * cy;

    unsigned long long accP[CPB / 2][4];
#pragma unroll
    for (int kp = 0; kp < CPB / 2; kp++) {
        const unsigned long long b2 = pk2(bias[oc0 + 2 * kp], bias[oc0 + 2 * kp + 1]);
#pragma unroll
        for (int j = 0; j < 4; j++) accP[kp][j] = b2;
    }

    const float* ip = inz + y * PW + x;   // even offset -> 8B aligned
    const float2* wp = reinterpret_cast<const float2*>(ws2);
    for (int c = 0; c < FD; c++) {
        float v[4][4];
#pragma unroll
        for (int r = 0; r < 4; r++) {
            const float2 a = *reinterpret_cast<const float2*>(ip + r * PW);
            const float2 b = *reinterpret_cast<const float2*>(ip + r * PW + 2);
            v[r][0] = a.x; v[r][1] = a.y; v[r][2] = b.x; v[r][3] = b.y;
        }
        ip += PAN;
        unsigned long long pv[4][4];
#pragma unroll
        for (int r = 0; r < 4; r++)
#pragma unroll
            for (int s = 0; s < 4; s++)
                pv[r][s] = pk2(v[r][s], v[r][s]);

        const int wb = c * 9 * (CPB / 2);
#pragma unroll
        for (int kp = 0; kp < CPB / 2; kp++) {
#pragma unroll
            for (int r = 0; r < 3; r++)
#pragma unroll
                for (int s = 0; s < 3; s++) {
                    const float2 wv2 = wp[wb + (r * 3 + s) * (CPB / 2) + kp];
                    const unsigned long long wu = pk2(wv2.x, wv2.y);
                    accP[kp][0] = fma2(wu, pv[r][s],         accP[kp][0]);
                    accP[kp][1] = fma2(wu, pv[r][s + 1],     accP[kp][1]);
                    accP[kp][2] = fma2(wu, pv[r + 1][s],     accP[kp][2]);
                    accP[kp][3] = fma2(wu, pv[r + 1][s + 1], accP[kp][3]);
                }
        }
    }

#pragma unroll
    for (int kp = 0; kp < CPB / 2; kp++)
#pragma unroll
        for (int px = 0; px < 4; px++) {
            float lo, hi;
            upk2(accP[kp][px], lo, hi);
            if (RELU) { lo = fmaxf(lo, 0.0f); hi = fmaxf(hi, 0.0f); }
            const int yy = px >> 1, xx = px & 1;
            if (TO_PAD) {
                outp[(oc0 + 2 * kp) * PAN + (y + yy + 1) * PW + (x + xx + 1)] = lo;
                outp[(oc0 + 2 * kp + 1) * PAN + (y + yy + 1) * PW + (x + xx + 1)] = hi;
            } else {
                outp[(oc0 + 2 * kp) * AN + (y + yy) * WW + (x + xx)] = lo;
                outp[(oc0 + 2 * kp + 1) * AN + (y + yy) * WW + (x + xx)] = hi;
            }
        }
}

// ---------------- final conv 64->3, 4 threads/px + shfl reduce ---------------
__global__ __launch_bounds__(256) void convF2_k(
    const float* __restrict__ in, const float* __restrict__ w,
    const float* __restrict__ bias, float* __restrict__ out) {
    __shared__ float ws[3 * FD * 9];
    for (int i = threadIdx.x; i < 3 * FD * 9; i += 256) ws[i] = w[i];
    __syncthreads();
    const int tid = threadIdx.x;
    const int p   = blockIdx.x * 64 + (tid >> 2);
    const int cc  = tid & 3;
    const int y = p / WW, x = p % WW;
    float acc[3] = {0.0f, 0.0f, 0.0f};
    const float* ip = in + (long)(cc * 16) * PAN + y * PW + x;
    const int cbase = cc * 16;
    for (int c = 0; c < 16; c++) {
        float v[9];
#pragma unroll
        for (int r = 0; r < 3; r++)
#pragma unroll
            for (int s = 0; s < 3; s++) v[r * 3 + s] = ip[r * PW + s];
        ip += PAN;
#pragma unroll
        for (int k = 0; k < 3; k++) {
            const float* wk = ws + (k * FD + cbase + c) * 9;
#pragma unroll
            for (int j = 0; j < 9; j++) acc[k] += wk[j] * v[j];
        }
    }
#pragma unroll
    for (int k = 0; k < 3; k++) {
        acc[k] += __shfl_xor_sync(0xFFFFFFFFu, acc[k], 1);
        acc[k] += __shfl_xor_sync(0xFFFFFFFFu, acc[k], 2);
    }
    if (cc == 0)
#pragma unroll
        for (int k = 0; k < 3; k++) out[k * AN + p] = acc[k] + bias[k];
}

// -------- ALL projections in one launch ---------------------------------------
__global__ __launch_bounds__(256) void projall_k(
    const float* __restrict__ f, const float* __restrict__ q_w, const float* __restrict__ q_b,
    const float* __restrict__ k_w, const float* __restrict__ k_b,
    const float* __restrict__ v_w, const float* __restrict__ v_b,
    __nv_bfloat16* __restrict__ QT, __nv_bfloat16* __restrict__ KT1,
    __nv_bfloat16* __restrict__ KT3,
    __nv_bfloat16* __restrict__ V1, __nv_bfloat16* __restrict__ V3) {
    const int zz = blockIdx.y;
    const int tid = threadIdx.x;

    if (zz < 3) {
        const float* in = (zz == 0) ? (f + (long)FD * AN) : (zz == 1) ? f : (f + 2L * FD * AN);
        const float* w  = (zz == 0) ? q_w : k_w;
        const float* b  = (zz == 0) ? q_b : k_b;
        __nv_bfloat16* out = (zz == 0) ? QT : (zz == 1) ? KT1 : KT3;
        const float scale = (zz == 0) ? 1.4426950408889634f : 1.0f;

        __shared__ float ws8[8 * FD];
        for (int i = tid; i < 8 * FD; i += 256) ws8[i] = w[i] * scale;
        __syncthreads();

        const int p  = tid >> 2;
        const int cc = tid & 3;
        const int n  = blockIdx.x * 64 + p;

        float acc[8] = {0, 0, 0, 0, 0, 0, 0, 0};
        const int c0 = cc * 16;
#pragma unroll
        for (int c = c0; c < c0 + 16; c++) {
            const float x = in[c * AN + n];
#pragma unroll
            for (int o = 0; o < 8; o++) acc[o] += ws8[o * FD + c] * x;
        }
#pragma unroll
        for (int o = 0; o < 8; o++) {
            acc[o] += __shfl_xor_sync(0xFFFFFFFFu, acc[o], 1);
            acc[o] += __shfl_xor_sync(0xFFFFFFFFu, acc[o], 2);
        }
        if (cc == 0) {
            uint32_t pk[4];
#pragma unroll
            for (int i = 0; i < 4; i++)
                pk[i] = pkbf(acc[2 * i] + b[2 * i] * scale,
                             acc[2 * i + 1] + b[2 * i + 1] * scale);
            reinterpret_cast<uint4*>(out)[n] = make_uint4(pk[0], pk[1], pk[2], pk[3]);
        }
    } else {
        __shared__ float sin_[FD][64];
        __shared__ float sw[FD * FD];
        __shared__ float sb[FD];
        const float* in = (zz == 4) ? (f + 2L * FD * AN) : f;
        __nv_bfloat16* out = (zz == 4) ? V3 : V1;
        const int n0 = blockIdx.x * 64;

        for (int i = tid; i < FD * FD; i += 256) sw[i] = v_w[i];
        if (tid < FD) sb[tid] = v_b[tid];
#pragma unroll
        for (int p = 0; p < 4; p++) {
            const int idx = tid + p * 256;
            const int c = idx >> 4, q = idx & 15;
            *reinterpret_cast<float4*>(&sin_[c][q * 4]) =
                *reinterpret_cast<const float4*>(in + c * AN + n0 + q * 4);
        }
        __syncthreads();

        const int px = tid & 31;
        const int og = tid >> 5;
        float acc[8][2];
#pragma unroll
        for (int o = 0; o < 8; o++) {
            acc[o][0] = sb[og * 8 + o];
            acc[o][1] = acc[o][0];
        }
#pragma unroll
        for (int c = 0; c < FD; c++) {
            const float x0 = sin_[c][px], x1 = sin_[c][px + 32];
#pragma unroll
            for (int o = 0; o < 8; o++) {
                const float wv = sw[(og * 8 + o) * FD + c];
                acc[o][0] += wv * x0;
                acc[o][1] += wv * x1;
            }
        }
        uint32_t pk0[4], pk1[4];
#pragma unroll
        for (int i = 0; i < 4; i++) {
            pk0[i] = pkbf(acc[2 * i][0], acc[2 * i + 1][0]);
            pk1[i] = pkbf(acc[2 * i][1], acc[2 * i + 1][1]);
        }
        *reinterpret_cast<uint4*>(out + (long)(n0 + px) * FD + og * 8) =
            make_uint4(pk0[0], pk0[1], pk0[2], pk0[3]);
        *reinterpret_cast<uint4*>(out + (long)(n0 + px + 32) * FD + og * 8) =
            make_uint4(pk1[0], pk1[1], pk1[2], pk1[3]);
    }
}

// ---------------- mma.sync flash cross-attention, key-split ------------------
// 3 CTAs/SM (84-reg budget): no S software-pipeline (saves regs), poly exp,
// K fragments prefetched one chunk ahead, V double-buffered via cp.async.
// Arithmetic order identical to R12 (bit-identical output).
__global__ __launch_bounds__(256, 3) void attn_mma_k(
    const __nv_bfloat16* __restrict__ qt,
    const __nv_bfloat16* __restrict__ kt1, const __nv_bfloat16* __restrict__ v1,
    const __nv_bfloat16* __restrict__ kt3, const __nv_bfloat16* __restrict__ v3,
    float* __restrict__ oP, float* __restrict__ rsP) {

    __shared__ __align__(128) __nv_bfloat16 sv[2][128 * FD];   // 2 x 16 KB V tiles

    const __nv_bfloat16* kt = blockIdx.y ? kt3 : kt1;
    const __nv_bfloat16* v  = blockIdx.y ? v3  : v1;
    const int part = blockIdx.y * 2 + blockIdx.z;
    float* out = oP  + (long)part * FD * AN;
    float* rso = rsP + part * AN;

    const int tid  = threadIdx.x;
    const int wid  = tid >> 5;
    const int lane = tid & 31;
    const int gid  = lane >> 2;
    const int tig  = lane & 3;
    const int q0   = blockIdx.x * 128;
    const int qb   = q0 + wid * 16;
    const int t0   = blockIdx.z * 36;

    const uint32_t qa0 = *reinterpret_cast<const uint32_t*>(qt + (qb + gid) * 8 + tig * 2);
    const uint32_t qa1 = *reinterpret_cast<const uint32_t*>(qt + (qb + 8 + gid) * 8 + tig * 2);

    float o[8][4];
#pragma unroll
    for (int i = 0; i < 8; i++)
#pragma unroll
        for (int j = 0; j < 4; j++) o[i][j] = 0.0f;

    // 2^x Taylor coefficients (splat into both f32x2 lanes)
    const unsigned long long C1  = pk2(0.6931471805599453f, 0.6931471805599453f);
    const unsigned long long C2  = pk2(0.2402265069591007f, 0.2402265069591007f);
    const unsigned long long C3  = pk2(0.0555041086648216f, 0.0555041086648216f);
    const unsigned long long ONE = pk2(1.0f, 1.0f);
    unsigned long long rsL = 0ULL, rsH = 0ULL;   // packed rowsum accumulators

    const uint32_t svb = smem_u32(&sv[0][0]);
    const int lm_m = lane >> 3, lm_r = lane & 7;
    const int lm_krow_off = (lm_m & 1) * 8 + lm_r;
    const int lm_c16_off  = lm_m >> 1;
    const int K7 = lm_krow_off & 7;
    uint32_t lmoff[4];
#pragma unroll
    for (int np = 0; np < 4; np++)
        lmoff[np] = (uint32_t)(lm_krow_off * 128 +
                               (((np * 2 + lm_c16_off) ^ K7) << 4));

    const int vkey = tid >> 3, vc16 = tid & 7;
    const uint32_t vdst0 = svb + (uint32_t)(vkey * 128 + ((vc16 ^ (vkey & 7)) << 4));
    const __nv_bfloat16* vsrc = v + (size_t)(t0 * 128 + vkey) * FD + vc16 * 8;

    cpa16(vdst0,         vsrc);
    cpa16(vdst0 + 4096,  vsrc + 32 * FD);
    cpa16(vdst0 + 8192,  vsrc + 64 * FD);
    cpa16(vdst0 + 12288, vsrc + 96 * FD);
    CPA_COMMIT();
    vsrc += 128 * FD;
    CPA_WAIT0();
    __syncthreads();

    // K fragments for chunk 0; rolling pointer for prefetch
    const __nv_bfloat16* kp = kt + (size_t)(t0 * 128 + gid) * 8;
    uint32_t kbA = *reinterpret_cast<const uint32_t*>(kp + tig * 2);
    uint32_t kbB = *reinterpret_cast<const uint32_t*>(kp + 64 + tig * 2);
    int cc_left = 36 * 8 - 1;

    for (int t = 0; t < 36; t++) {
        if (t < 35) {
            const uint32_t d = vdst0 + (uint32_t)(((t + 1) & 1) * 16384);
            cpa16(d,         vsrc);
            cpa16(d + 4096,  vsrc + 32 * FD);
            cpa16(d + 8192,  vsrc + 64 * FD);
            cpa16(d + 12288, vsrc + 96 * FD);
            CPA_COMMIT();
            vsrc += 128 * FD;
        }
        const uint32_t svread = svb + (uint32_t)((t & 1) * 16384);

#pragma unroll
        for (int j = 0; j < 8; j++) {
            float SA[4] = {0, 0, 0, 0}, SB[4] = {0, 0, 0, 0};
            mma_s8(SA, qa0, qa1, kbA);
            mma_s8(SB, qa0, qa1, kbB);

            // prefetch next chunk's K fragments (covers exp/pv section)
            const __nv_bfloat16* kpn = kp + ((cc_left > 0) ? 128 : 0);
            const uint32_t nA = *reinterpret_cast<const uint32_t*>(kpn + tig * 2);
            const uint32_t nB = *reinterpret_cast<const uint32_t*>(kpn + 64 + tig * 2);
            cc_left--;

            // packed poly 2^s, rowsum, pack bf16 (order identical to R12)
            const unsigned long long s01 = pk2(SA[0], SA[1]);
            const unsigned long long s23 = pk2(SA[2], SA[3]);
            const unsigned long long s45 = pk2(SB[0], SB[1]);
            const unsigned long long s67 = pk2(SB[2], SB[3]);
            const unsigned long long p01 =
                fma2(s01, fma2(s01, fma2(s01, C3, C2), C1), ONE);
            const unsigned long long p23 =
                fma2(s23, fma2(s23, fma2(s23, C3, C2), C1), ONE);
            const unsigned long long p45 =
                fma2(s45, fma2(s45, fma2(s45, C3, C2), C1), ONE);
            const unsigned long long p67 =
                fma2(s67, fma2(s67, fma2(s67, C3, C2), C1), ONE);
            rsL = add2(rsL, p01); rsL = add2(rsL, p45);
            rsH = add2(rsH, p23); rsH = add2(rsH, p67);
            uint32_t pa[4];
            float u0, u1;
            upk2(p01, u0, u1); pa[0] = pkbf(u0, u1);
            upk2(p23, u0, u1); pa[1] = pkbf(u0, u1);
            upk2(p45, u0, u1); pa[2] = pkbf(u0, u1);
            upk2(p67, u0, u1); pa[3] = pkbf(u0, u1);

            const uint32_t rowb = svread + (uint32_t)(j * 2048);
#pragma unroll
            for (int np = 0; np < 4; np++) {
                uint32_t vb[4];
                ldsm4t(vb, rowb + lmoff[np]);
                mma_pv(o[2 * np],     pa, vb[0], vb[1]);
                mma_pv(o[2 * np + 1], pa, vb[2], vb[3]);
            }
            kbA = nA; kbB = nB; kp = kpn;
        }

        if (t < 35) CPA_WAIT0();
        __syncthreads();
    }

    float a0, a1;
    upk2(rsL, a0, a1);
    float rs_lo = a0 + a1;
    upk2(rsH, a0, a1);
    float rs_hi = a0 + a1;
    rs_lo += __shfl_xor_sync(0xFFFFFFFFu, rs_lo, 1);
    rs_lo += __shfl_xor_sync(0xFFFFFFFFu, rs_lo, 2);
    rs_hi += __shfl_xor_sync(0xFFFFFFFFu, rs_hi, 1);
    rs_hi += __shfl_xor_sync(0xFFFFFFFFu, rs_hi, 2);

    const int row_lo = qb + gid, row_hi = qb + 8 + gid;
    if (tig == 0) { rso[row_lo] = rs_lo; rso[row_hi] = rs_hi; }
#pragma unroll
    for (int nt = 0; nt < 8; nt++) {
        const int ch = nt * 8 + tig * 2;
        out[ch * AN + row_lo]       = o[nt][0];
        out[(ch + 1) * AN + row_lo] = o[nt][1];
        out[ch * AN + row_hi]       = o[nt][2];
        out[(ch + 1) * AN + row_hi] = o[nt][3];
    }
}

// -------- combine key-split partials + normalize + fuse (writes PADDED) ------
__global__ void comb_fuse_k(const float* __restrict__ oP, const float* __restrict__ rsP,
                            const float* __restrict__ f2, float* __restrict__ out,
                            float* __restrict__ fh) {
    const int ch = blockIdx.y;
    if (blockIdx.x == 0) {
        zero_ring(out + (long)ch * PAN, threadIdx.x, 256);
        zero_ring(fh  + (long)ch * PAN, threadIdx.x, 256);
    }
    const int n  = blockIdx.x * blockDim.x + threadIdx.x;
    const long i = (long)ch * AN + n;
    const float inv1 = 1.0f / (rsP[n] + rsP[AN + n]);
    const float inv3 = 1.0f / (rsP[2 * AN + n] + rsP[3 * AN + n]);
    const float al1 = (oP[i] + oP[(long)FD * AN + i]) * inv1;
    const float al3 = (oP[2L * FD * AN + i] + oP[3L * FD * AN + i]) * inv3;
    const int y = n / WW, x = n % WW;
    out[(long)ch * PAN + (y + 1) * PW + (x + 1)] =
        (al1 + al3) * (1.0f / 3.0f) + f2[i];
}

// ---------------- launch ------------------------------------------------------
extern "C" void kernel_launch(void* const* d_in, const int* in_sizes, int n_in,
                              void* d_out, int out_size) {
    const float* l1     = (const float*)d_in[0];
    const float* l2     = (const float*)d_in[1];
    const float* l3     = (const float*)d_in[2];
    const float* ext_w1 = (const float*)d_in[3];
    const float* ext_b1 = (const float*)d_in[4];
    const float* ext_w2 = (const float*)d_in[5];
    const float* ext_b2 = (const float*)d_in[6];
    const float* q_w    = (const float*)d_in[7];
    const float* q_b    = (const float*)d_in[8];
    const float* k_w    = (const float*)d_in[9];
    const float* k_b    = (const float*)d_in[10];
    const float* v_w    = (const float*)d_in[11];
    const float* v_b    = (const float*)d_in[12];
    const float* fus_w1 = (const float*)d_in[13];
    const float* fus_b1 = (const float*)d_in[14];
    const float* fus_w2 = (const float*)d_in[15];
    const float* fus_b2 = (const float*)d_in[16];
    float* out = (float*)d_out;

    float *h, *f, *oP, *rsP, *fus, *fh;
    __nv_bfloat16 *QT, *KT1, *KT3, *V1, *V3;
    cudaGetSymbolAddress((void**)&h,   g_h);
    cudaGetSymbolAddress((void**)&f,   g_f);
    cudaGetSymbolAddress((void**)&QT,  g_QT);
    cudaGetSymbolAddress((void**)&KT1, g_KT1);
    cudaGetSymbolAddress((void**)&KT3, g_KT3);
    cudaGetSymbolAddress((void**)&V1,  g_V1);
    cudaGetSymbolAddress((void**)&V3,  g_V3);
    cudaGetSymbolAddress((void**)&oP,  g_oP);
    cudaGetSymbolAddress((void**)&rsP, g_rsP);
    cudaGetSymbolAddress((void**)&fus, g_fus);
    cudaGetSymbolAddress((void**)&fh,  g_fh);

    float* f2 = f + (long)FD * AN;

    // 1: conv 3->64 (+ h pad rings), batched over z
    convA_k<8><<<dim3(AN / 128, 8, 3), 128>>>(l1, l2, l3, ext_w1, ext_b1, h);
    // 2: conv 64->64 ext (3 images, packed f32x2, CPB=8 — best measured)
    convP_k<8, true, false><<<dim3(18, 8, 3), 128>>>(h, ext_w2, ext_b2, f);
    // 3: all projections
    projall_k<<<dim3(144, 5), 256>>>(f, q_w, q_b, k_w, k_b, v_w, v_b,
                                     QT, KT1, KT3, V1, V3);
    // 4: attention (ncu capture position) — 3 CTAs/SM
    attn_mma_k<<<dim3(AN / 128, 2, 2), 256>>>(QT, KT1, V1, KT3, V3, oP, rsP);
    // 5: combine + fuse (+ fus/fh pad rings)
    comb_fuse_k<<<dim3(AN / 256, FD), 256>>>(oP, rsP, f2, fus, fh);
    // 6: conv 64->64 fusion (packed f32x2, CPB=8)
    convP_k<8, true, true><<<dim3(18, 8, 1), 128>>>(fus, fus_w1, fus_b1, fh);
    // 7: conv 64->3 final (4 threads/px)
    convF2_k<<<dim3(AN / 64), 256>>>(fh, fus_w2, fus_b2, out);
}

// round 16
// speedup vs baseline: 1.1703x; 1.1703x over previous
#include <cuda_runtime.h>
#include <cuda_bf16.h>
#include <cstdint>

#define AN 9216      // N = 96*96
#define HH 96
#define WW 96
#define FD 64
#define PW 98        // padded width
#define PAN (PW*PW)  // padded plane = 9604

// ---------------- scratch (device globals; no allocation allowed) ------------
__device__ float g_h [3*FD*PAN];          // padded extractor hidden
__device__ float g_f [3*FD*AN];           // features f1,f2,f3 (unpadded)
__device__ __nv_bfloat16 g_QT [AN*8];     // [n][8] (pre-scaled by log2e)
__device__ __nv_bfloat16 g_KT1[AN*8];
__device__ __nv_bfloat16 g_KT3[AN*8];
__device__ __nv_bfloat16 g_V1 [AN*FD];    // [key][64]
__device__ __nv_bfloat16 g_V3 [AN*FD];
__device__ float g_oP [4*FD*AN];          // partial O: [pca*2+half][ch][n]
__device__ float g_rsP[4*AN];             // partial rowsums
__device__ float g_fus[FD*PAN];           // padded
__device__ float g_fh [FD*PAN];           // padded

// ---------------- helpers -----------------------------------------------------
__device__ __forceinline__ uint32_t smem_u32(const void* p) {
    uint32_t a;
    asm("{ .reg .u64 t; cvta.to.shared.u64 t, %1; cvt.u32.u64 %0, t; }" : "=r"(a) : "l"(p));
    return a;
}
__device__ __forceinline__ unsigned long long pk2(float lo, float hi) {
    unsigned long long r;
    asm("mov.b64 %0, {%1, %2};" : "=l"(r) : "f"(lo), "f"(hi));
    return r;
}
__device__ __forceinline__ void upk2(unsigned long long v, float& lo, float& hi) {
    asm("mov.b64 {%0, %1}, %2;" : "=f"(lo), "=f"(hi) : "l"(v));
}
__device__ __forceinline__ unsigned long long fma2(unsigned long long a,
                                                   unsigned long long b,
                                                   unsigned long long c) {
    unsigned long long d;
    asm("fma.rn.f32x2 %0, %1, %2, %3;" : "=l"(d) : "l"(a), "l"(b), "l"(c));
    return d;
}
__device__ __forceinline__ unsigned long long add2(unsigned long long a,
                                                   unsigned long long b) {
    unsigned long long d;
    asm("add.rn.f32x2 %0, %1, %2;" : "=l"(d) : "l"(a), "l"(b));
    return d;
}
__device__ __forceinline__ void mma_s8(float c[4], uint32_t a0, uint32_t a1, uint32_t b) {
    asm("mma.sync.aligned.m16n8k8.row.col.f32.bf16.bf16.f32 "
        "{%0,%1,%2,%3},{%4,%5},{%6},{%0,%1,%2,%3};"
        : "+f"(c[0]), "+f"(c[1]), "+f"(c[2]), "+f"(c[3])
        : "r"(a0), "r"(a1), "r"(b));
}
__device__ __forceinline__ void mma_pv(float c[4], const uint32_t a[4], uint32_t b0, uint32_t b1) {
    asm("mma.sync.aligned.m16n8k16.row.col.f32.bf16.bf16.f32 "
        "{%0,%1,%2,%3},{%4,%5,%6,%7},{%8,%9},{%0,%1,%2,%3};"
        : "+f"(c[0]), "+f"(c[1]), "+f"(c[2]), "+f"(c[3])
        : "r"(a[0]), "r"(a[1]), "r"(a[2]), "r"(a[3]), "r"(b0), "r"(b1));
}
__device__ __forceinline__ void ldsm4t(uint32_t r[4], uint32_t addr) {
    asm volatile("ldmatrix.sync.aligned.m8n8.x4.trans.shared.b16 {%0,%1,%2,%3}, [%4];"
                 : "=r"(r[0]), "=r"(r[1]), "=r"(r[2]), "=r"(r[3]) : "r"(addr));
}
__device__ __forceinline__ uint32_t pkbf(float lo, float hi) {
    __nv_bfloat162 h2 = __floats2bfloat162_rn(lo, hi);
    return *reinterpret_cast<uint32_t*>(&h2);
}
__device__ __forceinline__ void cpa16(uint32_t dst, const void* src) {
    asm volatile("cp.async.cg.shared.global [%0], [%1], 16;" :: "r"(dst), "l"(src) : "memory");
}
#define CPA_COMMIT() asm volatile("cp.async.commit_group;" ::: "memory")
#define CPA_WAIT0()  asm volatile("cp.async.wait_group 0;" ::: "memory")

// zero one padded plane's ring (388 elems) with nt threads
__device__ __forceinline__ void zero_ring(float* base, int t, int nt) {
    for (int i = t; i < 388; i += nt) {
        if (i < 98)       base[i] = 0.0f;
        else if (i < 196) base[97 * PW + (i - 98)] = 0.0f;
        else if (i < 292) base[(i - 196 + 1) * PW] = 0.0f;
        else              base[(i - 292 + 1) * PW + 97] = 0.0f;
    }
}

// ---------------- conv 3->64 from raw NCHW input, writes PADDED --------------
template<int CPB>
__global__ void convA_k(const float* __restrict__ in0, const float* __restrict__ in1,
                        const float* __restrict__ in2,
                        const float* __restrict__ w, const float* __restrict__ bias,
                        float* __restrict__ out) {
    __shared__ float ws[CPB * 3 * 9];
    const int oc0 = blockIdx.y * CPB;
    for (int i = threadIdx.x; i < CPB * 3 * 9; i += blockDim.x)
        ws[i] = w[oc0 * 3 * 9 + i];
    __syncthreads();

    const int z = blockIdx.z;
    const float* in = (z == 0) ? in0 : (z == 1) ? in1 : in2;
    float* outp = out + (long)z * FD * PAN;

    if (blockIdx.x < 8)
        zero_ring(outp + (long)(oc0 + blockIdx.x) * PAN, threadIdx.x, 128);

    const int p = blockIdx.x * blockDim.x + threadIdx.x;
    const int y = p / WW, x = p % WW;

    float acc[CPB];
#pragma unroll
    for (int k = 0; k < CPB; k++) acc[k] = bias[oc0 + k];

#pragma unroll
    for (int c = 0; c < 3; c++) {
        float v[9];
#pragma unroll
        for (int dy = 0; dy < 3; dy++) {
            const int yy = y + dy - 1;
#pragma unroll
            for (int dx = 0; dx < 3; dx++) {
                const int xx = x + dx - 1;
                v[dy * 3 + dx] = (yy >= 0 && yy < HH && xx >= 0 && xx < WW)
                                     ? in[c * AN + yy * WW + xx] : 0.0f;
            }
        }
#pragma unroll
        for (int k = 0; k < CPB; k++) {
            const float* wk = ws + k * 27 + c * 9;
#pragma unroll
            for (int j = 0; j < 9; j++) acc[k] += wk[j] * v[j];
        }
    }
#pragma unroll
    for (int k = 0; k < CPB; k++)
        outp[(oc0 + k) * PAN + (y + 1) * PW + (x + 1)] = fmaxf(acc[k], 0.0f);
}

// ---------------- 64->COUT conv from PADDED input, 2x2 px/thread, f32x2 ------
// Channel-loop software pipeline: prefetch channel c+1's 4x4 input window
// while channel c's fma2 block executes (hides L2 LDG latency at low occ).
template<int CPB, bool RELU, bool TO_PAD>
__global__ __launch_bounds__(128) void convP_k(
    const float* __restrict__ in, const float* __restrict__ w,
    const float* __restrict__ bias, float* __restrict__ out) {
    __shared__ __align__(8) float ws2[FD * 9 * CPB];   // [c*9+j][k]
    const int oc0 = blockIdx.y * CPB;
    for (int i = threadIdx.x; i < CPB * FD * 9; i += blockDim.x) {
        const int k = i / (FD * 9), rem = i % (FD * 9);
        ws2[rem * CPB + k] = w[oc0 * FD * 9 + i];
    }
    __syncthreads();

    const float* inz  = in + (long)blockIdx.z * FD * PAN;
    float* outp = out + (long)blockIdx.z * FD * AN;

    const int cell = blockIdx.x * blockDim.x + threadIdx.x;   // 0..2303
    const int cx = cell % 48, cy = cell / 48;
    const int x = 2 * cx, y = 2 * cy;

    unsigned long long accP[CPB / 2][4];
#pragma unroll
    for (int kp = 0; kp < CPB / 2; kp++) {
        const unsigned long long b2 = pk2(bias[oc0 + 2 * kp], bias[oc0 + 2 * kp + 1]);
#pragma unroll
        for (int j = 0; j < 4; j++) accP[kp][j] = b2;
    }

    const float* ip = inz + y * PW + x;   // even offset -> 8B aligned
    const float2* wp = reinterpret_cast<const float2*>(ws2);

    // prologue: load channel 0's window
    float vc[4][4];
#pragma unroll
    for (int r = 0; r < 4; r++) {
        const float2 a = *reinterpret_cast<const float2*>(ip + r * PW);
        const float2 b = *reinterpret_cast<const float2*>(ip + r * PW + 2);
        vc[r][0] = a.x; vc[r][1] = a.y; vc[r][2] = b.x; vc[r][3] = b.y;
    }
    ip += PAN;

    for (int c = 0; c < FD; c++) {
        // prefetch channel c+1 (guarded; latency covered by fma2 block below)
        float vn[4][4];
        if (c < FD - 1) {
#pragma unroll
            for (int r = 0; r < 4; r++) {
                const float2 a = *reinterpret_cast<const float2*>(ip + r * PW);
                const float2 b = *reinterpret_cast<const float2*>(ip + r * PW + 2);
                vn[r][0] = a.x; vn[r][1] = a.y; vn[r][2] = b.x; vn[r][3] = b.y;
            }
        }
        ip += PAN;

        unsigned long long pv[4][4];
#pragma unroll
        for (int r = 0; r < 4; r++)
#pragma unroll
            for (int s = 0; s < 4; s++)
                pv[r][s] = pk2(vc[r][s], vc[r][s]);

        const int wb = c * 9 * (CPB / 2);
#pragma unroll
        for (int kp = 0; kp < CPB / 2; kp++) {
#pragma unroll
            for (int r = 0; r < 3; r++)
#pragma unroll
                for (int s = 0; s < 3; s++) {
                    const float2 wv2 = wp[wb + (r * 3 + s) * (CPB / 2) + kp];
                    const unsigned long long wu = pk2(wv2.x, wv2.y);
                    accP[kp][0] = fma2(wu, pv[r][s],         accP[kp][0]);
                    accP[kp][1] = fma2(wu, pv[r][s + 1],     accP[kp][1]);
                    accP[kp][2] = fma2(wu, pv[r + 1][s],     accP[kp][2]);
                    accP[kp][3] = fma2(wu, pv[r + 1][s + 1], accP[kp][3]);
                }
        }

        // roll window
#pragma unroll
        for (int r = 0; r < 4; r++)
#pragma unroll
            for (int s = 0; s < 4; s++)
                vc[r][s] = vn[r][s];
    }

#pragma unroll
    for (int kp = 0; kp < CPB / 2; kp++)
#pragma unroll
        for (int px = 0; px < 4; px++) {
            float lo, hi;
            upk2(accP[kp][px], lo, hi);
            if (RELU) { lo = fmaxf(lo, 0.0f); hi = fmaxf(hi, 0.0f); }
            const int yy = px >> 1, xx = px & 1;
            if (TO_PAD) {
                outp[(oc0 + 2 * kp) * PAN + (y + yy + 1) * PW + (x + xx + 1)] = lo;
                outp[(oc0 + 2 * kp + 1) * PAN + (y + yy + 1) * PW + (x + xx + 1)] = hi;
            } else {
                outp[(oc0 + 2 * kp) * AN + (y + yy) * WW + (x + xx)] = lo;
                outp[(oc0 + 2 * kp + 1) * AN + (y + yy) * WW + (x + xx)] = hi;
            }
        }
}

// ---------------- final conv 64->3, 4 threads/px + shfl reduce ---------------
__global__ __launch_bounds__(256) void convF2_k(
    const float* __restrict__ in, const float* __restrict__ w,
    const float* __restrict__ bias, float* __restrict__ out) {
    __shared__ float ws[3 * FD * 9];
    for (int i = threadIdx.x; i < 3 * FD * 9; i += 256) ws[i] = w[i];
    __syncthreads();
    const int tid = threadIdx.x;
    const int p   = blockIdx.x * 64 + (tid >> 2);
    const int cc  = tid & 3;
    const int y = p / WW, x = p % WW;
    float acc[3] = {0.0f, 0.0f, 0.0f};
    const float* ip = in + (long)(cc * 16) * PAN + y * PW + x;
    const int cbase = cc * 16;
    for (int c = 0; c < 16; c++) {
        float v[9];
#pragma unroll
        for (int r = 0; r < 3; r++)
#pragma unroll
            for (int s = 0; s < 3; s++) v[r * 3 + s] = ip[r * PW + s];
        ip += PAN;
#pragma unroll
        for (int k = 0; k < 3; k++) {
            const float* wk = ws + (k * FD + cbase + c) * 9;
#pragma unroll
            for (int j = 0; j < 9; j++) acc[k] += wk[j] * v[j];
        }
    }
#pragma unroll
    for (int k = 0; k < 3; k++) {
        acc[k] += __shfl_xor_sync(0xFFFFFFFFu, acc[k], 1);
        acc[k] += __shfl_xor_sync(0xFFFFFFFFu, acc[k], 2);
    }
    if (cc == 0)
#pragma unroll
        for (int k = 0; k < 3; k++) out[k * AN + p] = acc[k] + bias[k];
}

// -------- ALL projections in one launch ---------------------------------------
__global__ __launch_bounds__(256) void projall_k(
    const float* __restrict__ f, const float* __restrict__ q_w, const float* __restrict__ q_b,
    const float* __restrict__ k_w, const float* __restrict__ k_b,
    const float* __restrict__ v_w, const float* __restrict__ v_b,
    __nv_bfloat16* __restrict__ QT, __nv_bfloat16* __restrict__ KT1,
    __nv_bfloat16* __restrict__ KT3,
    __nv_bfloat16* __restrict__ V1, __nv_bfloat16* __restrict__ V3) {
    const int zz = blockIdx.y;
    const int tid = threadIdx.x;

    if (zz < 3) {
        const float* in = (zz == 0) ? (f + (long)FD * AN) : (zz == 1) ? f : (f + 2L * FD * AN);
        const float* w  = (zz == 0) ? q_w : k_w;
        const float* b  = (zz == 0) ? q_b : k_b;
        __nv_bfloat16* out = (zz == 0) ? QT : (zz == 1) ? KT1 : KT3;
        const float scale = (zz == 0) ? 1.4426950408889634f : 1.0f;

        __shared__ float ws8[8 * FD];
        for (int i = tid; i < 8 * FD; i += 256) ws8[i] = w[i] * scale;
        __syncthreads();

        const int p  = tid >> 2;
        const int cc = tid & 3;
        const int n  = blockIdx.x * 64 + p;

        float acc[8] = {0, 0, 0, 0, 0, 0, 0, 0};
        const int c0 = cc * 16;
#pragma unroll
        for (int c = c0; c < c0 + 16; c++) {
            const float x = in[c * AN + n];
#pragma unroll
            for (int o = 0; o < 8; o++) acc[o] += ws8[o * FD + c] * x;
        }
#pragma unroll
        for (int o = 0; o < 8; o++) {
            acc[o] += __shfl_xor_sync(0xFFFFFFFFu, acc[o], 1);
            acc[o] += __shfl_xor_sync(0xFFFFFFFFu, acc[o], 2);
        }
        if (cc == 0) {
            uint32_t pk[4];
#pragma unroll
            for (int i = 0; i < 4; i++)
                pk[i] = pkbf(acc[2 * i] + b[2 * i] * scale,
                             acc[2 * i + 1] + b[2 * i + 1] * scale);
            reinterpret_cast<uint4*>(out)[n] = make_uint4(pk[0], pk[1], pk[2], pk[3]);
        }
    } else {
        __shared__ float sin_[FD][64];
        __shared__ float sw[FD * FD];
        __shared__ float sb[FD];
        const float* in = (zz == 4) ? (f + 2L * FD * AN) : f;
        __nv_bfloat16* out = (zz == 4) ? V3 : V1;
        const int n0 = blockIdx.x * 64;

        for (int i = tid; i < FD * FD; i += 256) sw[i] = v_w[i];
        if (tid < FD) sb[tid] = v_b[tid];
#pragma unroll
        for (int p = 0; p < 4; p++) {
            const int idx = tid + p * 256;
            const int c = idx >> 4, q = idx & 15;
            *reinterpret_cast<float4*>(&sin_[c][q * 4]) =
                *reinterpret_cast<const float4*>(in + c * AN + n0 + q * 4);
        }
        __syncthreads();

        const int px = tid & 31;
        const int og = tid >> 5;
        float acc[8][2];
#pragma unroll
        for (int o = 0; o < 8; o++) {
            acc[o][0] = sb[og * 8 + o];
            acc[o][1] = acc[o][0];
        }
#pragma unroll
        for (int c = 0; c < FD; c++) {
            const float x0 = sin_[c][px], x1 = sin_[c][px + 32];
#pragma unroll
            for (int o = 0; o < 8; o++) {
                const float wv = sw[(og * 8 + o) * FD + c];
                acc[o][0] += wv * x0;
                acc[o][1] += wv * x1;
            }
        }
        uint32_t pk0[4], pk1[4];
#pragma unroll
        for (int i = 0; i < 4; i++) {
            pk0[i] = pkbf(acc[2 * i][0], acc[2 * i + 1][0]);
            pk1[i] = pkbf(acc[2 * i][1], acc[2 * i + 1][1]);
        }
        *reinterpret_cast<uint4*>(out + (long)(n0 + px) * FD + og * 8) =
            make_uint4(pk0[0], pk0[1], pk0[2], pk0[3]);
        *reinterpret_cast<uint4*>(out + (long)(n0 + px + 32) * FD + og * 8) =
            make_uint4(pk1[0], pk1[1], pk1[2], pk1[3]);
    }
}

// ---------------- mma.sync flash cross-attention, key-split, pipelined -------
// R12 version (best measured): poly exp, 1-chunk software pipeline, 2 CTAs/SM.
__global__ __launch_bounds__(256, 2) void attn_mma_k(
    const __nv_bfloat16* __restrict__ qt,
    const __nv_bfloat16* __restrict__ kt1, const __nv_bfloat16* __restrict__ v1,
    const __nv_bfloat16* __restrict__ kt3, const __nv_bfloat16* __restrict__ v3,
    float* __restrict__ oP, float* __restrict__ rsP) {

    __shared__ __align__(128) __nv_bfloat16 sv[2][128 * FD];   // 2 x 16 KB V tiles

    const __nv_bfloat16* kt = blockIdx.y ? kt3 : kt1;
    const __nv_bfloat16* v  = blockIdx.y ? v3  : v1;
    const int part = blockIdx.y * 2 + blockIdx.z;
    float* out = oP  + (long)part * FD * AN;
    float* rso = rsP + part * AN;

    const int tid  = threadIdx.x;
    const int wid  = tid >> 5;
    const int lane = tid & 31;
    const int gid  = lane >> 2;
    const int tig  = lane & 3;
    const int q0   = blockIdx.x * 128;
    const int qb   = q0 + wid * 16;
    const int t0   = blockIdx.z * 36;

    const uint32_t qa0 = *reinterpret_cast<const uint32_t*>(qt + (qb + gid) * 8 + tig * 2);
    const uint32_t qa1 = *reinterpret_cast<const uint32_t*>(qt + (qb + 8 + gid) * 8 + tig * 2);

    float o[8][4];
#pragma unroll
    for (int i = 0; i < 8; i++)
#pragma unroll
        for (int j = 0; j < 4; j++) o[i][j] = 0.0f;

    // 2^x Taylor coefficients (splat into both f32x2 lanes)
    const unsigned long long C1  = pk2(0.6931471805599453f, 0.6931471805599453f);
    const unsigned long long C2  = pk2(0.2402265069591007f, 0.2402265069591007f);
    const unsigned long long C3  = pk2(0.0555041086648216f, 0.0555041086648216f);
    const unsigned long long ONE = pk2(1.0f, 1.0f);
    unsigned long long rsL = 0ULL, rsH = 0ULL;   // packed rowsum accumulators

    const uint32_t svb = smem_u32(&sv[0][0]);
    const int lm_m = lane >> 3, lm_r = lane & 7;
    const int lm_krow_off = (lm_m & 1) * 8 + lm_r;
    const int lm_c16_off  = lm_m >> 1;
    const int K7 = lm_krow_off & 7;
    uint32_t lmoff[4];
#pragma unroll
    for (int np = 0; np < 4; np++)
        lmoff[np] = (uint32_t)(lm_krow_off * 128 +
                               (((np * 2 + lm_c16_off) ^ K7) << 4));

    const int vkey = tid >> 3, vc16 = tid & 7;
    const uint32_t vdst0 = svb + (uint32_t)(vkey * 128 + ((vc16 ^ (vkey & 7)) << 4));
    const __nv_bfloat16* vsrc = v + (size_t)(t0 * 128 + vkey) * FD + vc16 * 8;

    cpa16(vdst0,         vsrc);
    cpa16(vdst0 + 4096,  vsrc + 32 * FD);
    cpa16(vdst0 + 8192,  vsrc + 64 * FD);
    cpa16(vdst0 + 12288, vsrc + 96 * FD);
    CPA_COMMIT();
    vsrc += 128 * FD;
    CPA_WAIT0();
    __syncthreads();

    // software pipeline prologue: S for chunk 0, K frags for chunk 1
    const __nv_bfloat16* kbase = kt + (size_t)(t0 * 128 + gid) * 8;
    uint32_t cA = *reinterpret_cast<const uint32_t*>(kbase + tig * 2);
    uint32_t cB = *reinterpret_cast<const uint32_t*>(kbase + 64 + tig * 2);
    uint32_t kb1A = *reinterpret_cast<const uint32_t*>(kbase + 128 + tig * 2);
    uint32_t kb1B = *reinterpret_cast<const uint32_t*>(kbase + 128 + 64 + tig * 2);
    const __nv_bfloat16* kp = kbase + 256;
    int cc_left = 287;

    float S0A[4] = {0, 0, 0, 0}, S0B[4] = {0, 0, 0, 0};
    mma_s8(S0A, qa0, qa1, cA);
    mma_s8(S0B, qa0, qa1, cB);

    for (int t = 0; t < 36; t++) {
        if (t < 35) {
            const uint32_t d = vdst0 + (uint32_t)(((t + 1) & 1) * 16384);
            cpa16(d,         vsrc);
            cpa16(d + 4096,  vsrc + 32 * FD);
            cpa16(d + 8192,  vsrc + 64 * FD);
            cpa16(d + 12288, vsrc + 96 * FD);
            CPA_COMMIT();
            vsrc += 128 * FD;
        }
        const uint32_t svread = svb + (uint32_t)((t & 1) * 16384);

#pragma unroll
        for (int j = 0; j < 8; j++) {
            // prefetch K frags for chunk c+2
            const uint32_t nA = *reinterpret_cast<const uint32_t*>(kp + tig * 2);
            const uint32_t nB = *reinterpret_cast<const uint32_t*>(kp + 64 + tig * 2);

            // S for chunk c+1 (fills tensor pipe while c is consumed)
            float S1A[4] = {0, 0, 0, 0}, S1B[4] = {0, 0, 0, 0};
            mma_s8(S1A, qa0, qa1, kb1A);
            mma_s8(S1B, qa0, qa1, kb1B);

            // consume chunk c: packed poly 2^s, rowsum, pack bf16, PV
            const unsigned long long s01 = pk2(S0A[0], S0A[1]);
            const unsigned long long s23 = pk2(S0A[2], S0A[3]);
            const unsigned long long s45 = pk2(S0B[0], S0B[1]);
            const unsigned long long s67 = pk2(S0B[2], S0B[3]);
            const unsigned long long p01 =
                fma2(s01, fma2(s01, fma2(s01, C3, C2), C1), ONE);
            const unsigned long long p23 =
                fma2(s23, fma2(s23, fma2(s23, C3, C2), C1), ONE);
            const unsigned long long p45 =
                fma2(s45, fma2(s45, fma2(s45, C3, C2), C1), ONE);
            const unsigned long long p67 =
                fma2(s67, fma2(s67, fma2(s67, C3, C2), C1), ONE);
            rsL = add2(rsL, p01); rsL = add2(rsL, p45);
            rsH = add2(rsH, p23); rsH = add2(rsH, p67);
            uint32_t pa[4];
            float u0, u1;
            upk2(p01, u0, u1); pa[0] = pkbf(u0, u1);
            upk2(p23, u0, u1); pa[1] = pkbf(u0, u1);
            upk2(p45, u0, u1); pa[2] = pkbf(u0, u1);
            upk2(p67, u0, u1); pa[3] = pkbf(u0, u1);

            const uint32_t rowb = svread + (uint32_t)(j * 2048);
#pragma unroll
            for (int np = 0; np < 4; np++) {
                uint32_t vb[4];
                ldsm4t(vb, rowb + lmoff[np]);
                mma_pv(o[2 * np],     pa, vb[0], vb[1]);
                mma_pv(o[2 * np + 1], pa, vb[2], vb[3]);
            }

            // roll pipeline state
#pragma unroll
            for (int i = 0; i < 4; i++) { S0A[i] = S1A[i]; S0B[i] = S1B[i]; }
            kb1A = nA; kb1B = nB;
            kp += (cc_left > 1) ? 128 : 0;
            cc_left--;
        }

        if (t < 35) CPA_WAIT0();
        __syncthreads();
    }

    float a0, a1;
    upk2(rsL, a0, a1);
    float rs_lo = a0 + a1;
    upk2(rsH, a0, a1);
    float rs_hi = a0 + a1;
    rs_lo += __shfl_xor_sync(0xFFFFFFFFu, rs_lo, 1);
    rs_lo += __shfl_xor_sync(0xFFFFFFFFu, rs_lo, 2);
    rs_hi += __shfl_xor_sync(0xFFFFFFFFu, rs_hi, 1);
    rs_hi += __shfl_xor_sync(0xFFFFFFFFu, rs_hi, 2);

    const int row_lo = qb + gid, row_hi = qb + 8 + gid;
    if (tig == 0) { rso[row_lo] = rs_lo; rso[row_hi] = rs_hi; }
#pragma unroll
    for (int nt = 0; nt < 8; nt++) {
        const int ch = nt * 8 + tig * 2;
        out[ch * AN + row_lo]       = o[nt][0];
        out[(ch + 1) * AN + row_lo] = o[nt][1];
        out[ch * AN + row_hi]       = o[nt][2];
        out[(ch + 1) * AN + row_hi] = o[nt][3];
    }
}

// -------- combine key-split partials + normalize + fuse (writes PADDED) ------
__global__ void comb_fuse_k(const float* __restrict__ oP, const float* __restrict__ rsP,
                            const float* __restrict__ f2, float* __restrict__ out,
                            float* __restrict__ fh) {
    const int ch = blockIdx.y;
    if (blockIdx.x == 0) {
        zero_ring(out + (long)ch * PAN, threadIdx.x, 256);
        zero_ring(fh  + (long)ch * PAN, threadIdx.x, 256);
    }
    const int n  = blockIdx.x * blockDim.x + threadIdx.x;
    const long i = (long)ch * AN + n;
    const float inv1 = 1.0f / (rsP[n] + rsP[AN + n]);
    const float inv3 = 1.0f / (rsP[2 * AN + n] + rsP[3 * AN + n]);
    const float al1 = (oP[i] + oP[(long)FD * AN + i]) * inv1;
    const float al3 = (oP[2L * FD * AN + i] + oP[3L * FD * AN + i]) * inv3;
    const int y = n / WW, x = n % WW;
    out[(long)ch * PAN + (y + 1) * PW + (x + 1)] =
        (al1 + al3) * (1.0f / 3.0f) + f2[i];
}

// ---------------- launch ------------------------------------------------------
extern "C" void kernel_launch(void* const* d_in, const int* in_sizes, int n_in,
                              void* d_out, int out_size) {
    const float* l1     = (const float*)d_in[0];
    const float* l2     = (const float*)d_in[1];
    const float* l3     = (const float*)d_in[2];
    const float* ext_w1 = (const float*)d_in[3];
    const float* ext_b1 = (const float*)d_in[4];
    const float* ext_w2 = (const float*)d_in[5];
    const float* ext_b2 = (const float*)d_in[6];
    const float* q_w    = (const float*)d_in[7];
    const float* q_b    = (const float*)d_in[8];
    const float* k_w    = (const float*)d_in[9];
    const float* k_b    = (const float*)d_in[10];
    const float* v_w    = (const float*)d_in[11];
    const float* v_b    = (const float*)d_in[12];
    const float* fus_w1 = (const float*)d_in[13];
    const float* fus_b1 = (const float*)d_in[14];
    const float* fus_w2 = (const float*)d_in[15];
    const float* fus_b2 = (const float*)d_in[16];
    float* out = (float*)d_out;

    float *h, *f, *oP, *rsP, *fus, *fh;
    __nv_bfloat16 *QT, *KT1, *KT3, *V1, *V3;
    cudaGetSymbolAddress((void**)&h,   g_h);
    cudaGetSymbolAddress((void**)&f,   g_f);
    cudaGetSymbolAddress((void**)&QT,  g_QT);
    cudaGetSymbolAddress((void**)&KT1, g_KT1);
    cudaGetSymbolAddress((void**)&KT3, g_KT3);
    cudaGetSymbolAddress((void**)&V1,  g_V1);
    cudaGetSymbolAddress((void**)&V3,  g_V3);
    cudaGetSymbolAddress((void**)&oP,  g_oP);
    cudaGetSymbolAddress((void**)&rsP, g_rsP);
    cudaGetSymbolAddress((void**)&fus, g_fus);
    cudaGetSymbolAddress((void**)&fh,  g_fh);

    float* f2 = f + (long)FD * AN;

    // 1: conv 3->64 (+ h pad rings), batched over z
    convA_k<8><<<dim3(AN / 128, 8, 3), 128>>>(l1, l2, l3, ext_w1, ext_b1, h);
    // 2: conv 64->64 ext (3 images, f32x2, channel-pipelined)
    convP_k<8, true, false><<<dim3(18, 8, 3), 128>>>(h, ext_w2, ext_b2, f);
    // 3: all projections
    projall_k<<<dim3(144, 5), 256>>>(f, q_w, q_b, k_w, k_b, v_w, v_b,
                                     QT, KT1, KT3, V1, V3);
    // 4: attention (ncu capture position) — R12 best version
    attn_mma_k<<<dim3(AN / 128, 2, 2), 256>>>(QT, KT1, V1, KT3, V3, oP, rsP);
    // 5: combine + fuse (+ fus/fh pad rings)
    comb_fuse_k<<<dim3(AN / 256, FD), 256>>>(oP, rsP, f2, fus, fh);
    // 6: conv 64->64 fusion (f32x2, channel-pipelined)
    convP_k<8, true, true><<<dim3(18, 8, 1), 128>>>(fus, fus_w1, fus_b1, fh);
    // 7: conv 64->3 final (4 threads/px)
    convF2_k<<<dim3(AN / 64), 256>>>(fh, fus_w2, fus_b2, out);
}